// round 10
// baseline (speedup 1.0000x reference)
#include <cuda_runtime.h>
#include <cuda_fp16.h>
#include <stdint.h>
#include <math.h>

// Problem constants (fixed shapes for this problem)
#define MAXN 20000
#define MAXE 320000
#define SED  768
#define HC1  512      // 4 heads * 128
#define C1   128
#define H1   4
#define C2   128

// ---------------- scratch (no allocation allowed; bss device globals) ----------------
__device__ __align__(16) float g_h1[MAXN * HC1];     // layer1 pre-attention features
__device__ __align__(16) float g_act1[MAXN * HC1];   // layer1 output after elu
__device__ __align__(16) float g_h3[MAXN * C2];      // layer2 pre-attention features
__device__ __align__(16) float g_esrc1[MAXN * 4];
__device__ __align__(16) float g_edst1[MAXN * 4];
__device__ float g_esrc2[MAXN];
__device__ float g_edst2[MAXN];
__device__ __align__(16) float g_c1[HC1];            // sent @ W1[768:] constant vector
__device__ int g_cnt[MAXN];
__device__ int g_rowptr[MAXN + 1];
__device__ int g_cursor[MAXN];
__device__ int g_col[MAXE];
__device__ int g_bsum[64];

__device__ __forceinline__ float lrelu(float x) { return x > 0.f ? x : 0.2f * x; }

__device__ __forceinline__ unsigned pack2(float x, float y) {
    __half2 h = __floats2half2_rn(x, y);
    return *(unsigned*)&h;
}

// ---------------- CSR build ----------------
__global__ void k_count(const int* __restrict__ ei, int E) {
    int i = blockIdx.x * blockDim.x + threadIdx.x;
    if (i < E) atomicAdd(&g_cnt[ei[E + i]], 1);
}

__global__ void k_scan1(int N) {
    __shared__ int sm[512];
    int b = blockIdx.x, t = threadIdx.x, i = b * 512 + t;
    int v = (i < N) ? g_cnt[i] : 0;
    sm[t] = v;
    __syncthreads();
#pragma unroll
    for (int off = 1; off < 512; off <<= 1) {
        int u = (t >= off) ? sm[t - off] : 0;
        __syncthreads();
        sm[t] += u;
        __syncthreads();
    }
    if (i < N) g_rowptr[i + 1] = sm[t];
    if (t == 511) g_bsum[b] = sm[511];
}

// finalize rowptr + cursor; block offset = sum of g_bsum[0..blk-1] (blk constant per block)
__global__ void k_scan3(int N) {
    __shared__ int soff;
    int i = blockIdx.x * 256 + threadIdx.x;
    int blk = (blockIdx.x * 256) >> 9;
    if (threadIdx.x == 0) {
        int s = 0;
        for (int b = 0; b < blk; b++) s += g_bsum[b];
        soff = s;
    }
    __syncthreads();
    if (i < N) {
        int r = g_rowptr[i + 1] + soff;
        g_rowptr[i + 1] = r;
        g_cursor[i] = r - g_cnt[i];
    }
    if (i == 0) g_rowptr[0] = 0;
}

__global__ void k_scatter(const int* __restrict__ ei, int E) {
    int i = blockIdx.x * blockDim.x + threadIdx.x;
    if (i < E) {
        int dst = ei[E + i], src = ei[i];
        int pos = atomicAdd(&g_cursor[dst], 1);
        g_col[pos] = src;
    }
}

// ---------------- constant vector: c1 += sent @ W1[768:1536, :] (k-chunked, atomicAdd) ----
__global__ void k_constvec(const float* __restrict__ sent, const float* __restrict__ W1) {
    int j = blockIdx.x * 128 + threadIdx.x;
    int k0 = blockIdx.y * 128;
    float s = 0.f;
#pragma unroll 4
    for (int k = k0; k < k0 + 128; k++)
        s += sent[k] * W1[(size_t)(SED + k) * HC1 + j];
    atomicAdd(&g_c1[j], s);
}

// ---------------- FP16 tensor-core GEMM (double-buffered, register-staged) --------------
// C[M,N] = A[M,K] @ B[K,N] (+ addv[col]). A,B converted to fp16 (RNE) during smem staging;
// mma.m16n8k16.f32.f16.f16.f32 (fp32 accumulate). fp16 mantissa == tf32 mantissa (11 bits),
// values here are O(1) so no range issues. N % 128 == 0, K % 16 == 0; M bounds-checked.
#define LDAH 12     // half2 words per A row (8 used + 4 pad): bank = 12g+t, conflict-free
#define LDBH 136    // half2 words per B kpair row (128 used + 8): bank = 8t+g, conflict-free
__global__ __launch_bounds__(256, 2)
void k_gemm_f16(const float* __restrict__ A, const float* __restrict__ B,
                float* __restrict__ C, const float* __restrict__ addv,
                int M, int N, int K) {
    __shared__ unsigned Ah[2][128 * LDAH];
    __shared__ unsigned Bh[2][8 * LDBH];

    int tid = threadIdx.x;
    int lane = tid & 31, wid = tid >> 5;
    int g = lane >> 2, t = lane & 3;
    int wm = (wid >> 2) * 64, wn = (wid & 3) * 32;
    int m0 = blockIdx.x * 128, n0 = blockIdx.y * 128;

    // A staging: thread -> row tid>>1, k-offset (tid&1)*4 (plus +8)
    int a_row = tid >> 1;
    int a_k   = (tid & 1) * 4;
    // B staging: thread -> kpair tid>>5 (rows 2kp, 2kp+1), 4 cols at (tid&31)*4
    int b_kp  = tid >> 5;
    int b_n   = (tid & 31) * 4;

    bool a_ok = (m0 + a_row) < M;
    const float* Aptr = A + (size_t)(m0 + a_row) * K;
    const float* Bptr = B + (size_t)n0;

    float acc[4][4][4];
#pragma unroll
    for (int mi = 0; mi < 4; mi++)
#pragma unroll
        for (int ni = 0; ni < 4; ni++)
#pragma unroll
            for (int c = 0; c < 4; c++) acc[mi][ni][c] = 0.f;

    float4 ra0, ra1, rb0, rb1;
    const float4 fz = make_float4(0.f, 0.f, 0.f, 0.f);

    // prologue: stage 0
    {
        ra0 = a_ok ? *(const float4*)&Aptr[a_k]     : fz;
        ra1 = a_ok ? *(const float4*)&Aptr[a_k + 8] : fz;
        rb0 = *(const float4*)&Bptr[(size_t)(2 * b_kp) * N + b_n];
        rb1 = *(const float4*)&Bptr[(size_t)(2 * b_kp + 1) * N + b_n];
        uint2 wa0; wa0.x = pack2(ra0.x, ra0.y); wa0.y = pack2(ra0.z, ra0.w);
        uint2 wa1; wa1.x = pack2(ra1.x, ra1.y); wa1.y = pack2(ra1.z, ra1.w);
        *(uint2*)&Ah[0][a_row * LDAH + (a_k >> 1)]     = wa0;
        *(uint2*)&Ah[0][a_row * LDAH + (a_k >> 1) + 4] = wa1;
        uint4 wb;
        wb.x = pack2(rb0.x, rb1.x); wb.y = pack2(rb0.y, rb1.y);
        wb.z = pack2(rb0.z, rb1.z); wb.w = pack2(rb0.w, rb1.w);
        *(uint4*)&Bh[0][b_kp * LDBH + b_n] = wb;
    }
    __syncthreads();

    int nk = K / 16;
    for (int kt = 0; kt < nk; kt++) {
        int cur = kt & 1;
        if (kt + 1 < nk) {
            int kb = (kt + 1) * 16;
            ra0 = a_ok ? *(const float4*)&Aptr[kb + a_k]     : fz;
            ra1 = a_ok ? *(const float4*)&Aptr[kb + a_k + 8] : fz;
            rb0 = *(const float4*)&Bptr[(size_t)(kb + 2 * b_kp) * N + b_n];
            rb1 = *(const float4*)&Bptr[(size_t)(kb + 2 * b_kp + 1) * N + b_n];
        }

        const unsigned* as = Ah[cur];
        const unsigned* bs = Bh[cur];
        {
            unsigned af[4][4];
#pragma unroll
            for (int mi = 0; mi < 4; mi++) {
                int r = wm + mi * 16 + g;
                af[mi][0] = as[r * LDAH + t];              // row g,   k 2t..2t+1
                af[mi][1] = as[(r + 8) * LDAH + t];        // row g+8, k 2t..2t+1
                af[mi][2] = as[r * LDAH + t + 4];          // row g,   k 8+2t..
                af[mi][3] = as[(r + 8) * LDAH + t + 4];    // row g+8, k 8+2t..
            }
#pragma unroll
            for (int ni = 0; ni < 4; ni++) {
                int cidx = wn + ni * 8 + g;
                unsigned b0 = bs[t * LDBH + cidx];         // k 2t..2t+1,   col g
                unsigned b1 = bs[(t + 4) * LDBH + cidx];   // k 8+2t..,     col g
#pragma unroll
                for (int mi = 0; mi < 4; mi++) {
                    asm volatile(
                        "mma.sync.aligned.m16n8k16.row.col.f32.f16.f16.f32 "
                        "{%0,%1,%2,%3}, {%4,%5,%6,%7}, {%8,%9}, {%0,%1,%2,%3};"
                        : "+f"(acc[mi][ni][0]), "+f"(acc[mi][ni][1]),
                          "+f"(acc[mi][ni][2]), "+f"(acc[mi][ni][3])
                        : "r"(af[mi][0]), "r"(af[mi][1]), "r"(af[mi][2]), "r"(af[mi][3]),
                          "r"(b0), "r"(b1));
                }
            }
        }

        if (kt + 1 < nk) {
            int nxt = (kt + 1) & 1;
            uint2 wa0; wa0.x = pack2(ra0.x, ra0.y); wa0.y = pack2(ra0.z, ra0.w);
            uint2 wa1; wa1.x = pack2(ra1.x, ra1.y); wa1.y = pack2(ra1.z, ra1.w);
            *(uint2*)&Ah[nxt][a_row * LDAH + (a_k >> 1)]     = wa0;
            *(uint2*)&Ah[nxt][a_row * LDAH + (a_k >> 1) + 4] = wa1;
            uint4 wb;
            wb.x = pack2(rb0.x, rb1.x); wb.y = pack2(rb0.y, rb1.y);
            wb.z = pack2(rb0.z, rb1.z); wb.w = pack2(rb0.w, rb1.w);
            *(uint4*)&Bh[nxt][b_kp * LDBH + b_n] = wb;
            __syncthreads();
        }
    }

    // epilogue: c0,c1 -> row g cols 2t,2t+1; c2,c3 -> row g+8
#pragma unroll
    for (int mi = 0; mi < 4; mi++) {
#pragma unroll
        for (int half = 0; half < 2; half++) {
            int r = m0 + wm + mi * 16 + g + half * 8;
            if (r < M) {
#pragma unroll
                for (int ni = 0; ni < 4; ni++) {
                    int c = n0 + wn + ni * 8 + 2 * t;
                    float2 v;
                    v.x = acc[mi][ni][half * 2 + 0];
                    v.y = acc[mi][ni][half * 2 + 1];
                    if (addv) { v.x += addv[c]; v.y += addv[c + 1]; }
                    *(float2*)&C[(size_t)r * N + c] = v;
                }
            }
        }
    }
}

// ---------------- attention dot products ----------------
__global__ void k_edot1(const float* __restrict__ a_src, const float* __restrict__ a_dst) {
    int n = blockIdx.x;
    int t = threadIdx.x, lane = t & 31, w = t >> 5;
    const float* hrow = &g_h1[(size_t)n * HC1 + w * C1];
    float s1 = 0.f, s2 = 0.f;
#pragma unroll
    for (int c = lane; c < C1; c += 32) {
        float v = hrow[c];
        s1 += v * a_src[w * C1 + c];
        s2 += v * a_dst[w * C1 + c];
    }
#pragma unroll
    for (int off = 16; off; off >>= 1) {
        s1 += __shfl_xor_sync(0xffffffffu, s1, off);
        s2 += __shfl_xor_sync(0xffffffffu, s2, off);
    }
    if (lane == 0) { g_esrc1[n * 4 + w] = s1; g_edst1[n * 4 + w] = s2; }
}

__global__ void k_edot2(const float* __restrict__ a_src, const float* __restrict__ a_dst, int N) {
    int t = threadIdx.x, lane = t & 31, w = t >> 5;
    int n = blockIdx.x * 4 + w;
    if (n >= N) return;
    const float* hrow = &g_h3[(size_t)n * C2];
    float s1 = 0.f, s2 = 0.f;
#pragma unroll
    for (int c = lane; c < C2; c += 32) {
        float v = hrow[c];
        s1 += v * a_src[c];
        s2 += v * a_dst[c];
    }
#pragma unroll
    for (int off = 16; off; off >>= 1) {
        s1 += __shfl_xor_sync(0xffffffffu, s1, off);
        s2 += __shfl_xor_sync(0xffffffffu, s2, off);
    }
    if (lane == 0) { g_esrc2[n] = s1; g_edst2[n] = s2; }
}

// ---------------- layer 1 aggregation: single-sweep normalization ----------------
__global__ void k_agg1(const float* __restrict__ b1) {
    int n = blockIdx.x;
    int t = threadIdx.x, lane = t & 31, w = t >> 5;
    int start = g_rowptr[n], end = g_rowptr[n + 1];
    float4 edv = *(const float4*)&g_edst1[n * 4];

    __shared__ float4 wbuf[128];
    __shared__ int scol[128];
    __shared__ float sred[4][4];

    float acc[4] = {0.f, 0.f, 0.f, 0.f};
    float ss[4]  = {0.f, 0.f, 0.f, 0.f};

    for (int base = start; base < end; base += 128) {
        int i = base + t;
        if (i < end) {
            int sc = g_col[i];
            float4 es = *(const float4*)&g_esrc1[sc * 4];
            float4 wv;
            wv.x = __expf(lrelu(es.x + edv.x));
            wv.y = __expf(lrelu(es.y + edv.y));
            wv.z = __expf(lrelu(es.z + edv.z));
            wv.w = __expf(lrelu(es.w + edv.w));
            ss[0] += wv.x; ss[1] += wv.y; ss[2] += wv.z; ss[3] += wv.w;
            wbuf[t] = wv;
            scol[t] = sc;
        }
        __syncthreads();
        int cnt = min(128, end - base);
        int j = 0;
        for (; j + 1 < cnt; j += 2) {
            int s0 = scol[j], s1 = scol[j + 1];
            float4 w0 = wbuf[j], w1 = wbuf[j + 1];
            const float* p0 = &g_h1[(size_t)s0 * HC1];
            const float* p1 = &g_h1[(size_t)s1 * HC1];
            float v00 = p0[t], v01 = p0[128 + t], v02 = p0[256 + t], v03 = p0[384 + t];
            float v10 = p1[t], v11 = p1[128 + t], v12 = p1[256 + t], v13 = p1[384 + t];
            acc[0] = fmaf(w0.x, v00, acc[0]);
            acc[1] = fmaf(w0.y, v01, acc[1]);
            acc[2] = fmaf(w0.z, v02, acc[2]);
            acc[3] = fmaf(w0.w, v03, acc[3]);
            acc[0] = fmaf(w1.x, v10, acc[0]);
            acc[1] = fmaf(w1.y, v11, acc[1]);
            acc[2] = fmaf(w1.z, v12, acc[2]);
            acc[3] = fmaf(w1.w, v13, acc[3]);
        }
        if (j < cnt) {
            int s0 = scol[j];
            float4 w0 = wbuf[j];
            const float* p0 = &g_h1[(size_t)s0 * HC1];
            acc[0] = fmaf(w0.x, p0[t],       acc[0]);
            acc[1] = fmaf(w0.y, p0[128 + t], acc[1]);
            acc[2] = fmaf(w0.z, p0[256 + t], acc[2]);
            acc[3] = fmaf(w0.w, p0[384 + t], acc[3]);
        }
        __syncthreads();
    }

#pragma unroll
    for (int h = 0; h < 4; h++)
#pragma unroll
        for (int off = 16; off; off >>= 1)
            ss[h] += __shfl_xor_sync(0xffffffffu, ss[h], off);
    if (lane == 0) { sred[0][w] = ss[0]; sred[1][w] = ss[1]; sred[2][w] = ss[2]; sred[3][w] = ss[3]; }
    __syncthreads();

    float* orow = &g_act1[(size_t)n * HC1];
#pragma unroll
    for (int h = 0; h < 4; h++) {
        float s = sred[h][0] + sred[h][1] + sred[h][2] + sred[h][3];
        float inv = (s > 0.f) ? 1.f / s : 0.f;   // deg-0 node -> out = bias
        float v = acc[h] * inv + b1[h * C1 + t];
        orow[h * C1 + t] = v > 0.f ? v : expm1f(v);
    }
}

// ---------------- layer 2 aggregation -> final output ----------------
__global__ void k_agg2(const float* __restrict__ b2, float* __restrict__ out) {
    int n = blockIdx.x;
    int t = threadIdx.x, lane = t & 31, w = t >> 5;
    int start = g_rowptr[n], end = g_rowptr[n + 1];
    float ed = g_edst2[n];

    __shared__ float wbuf[128];
    __shared__ int scol[128];
    __shared__ float sred[4];

    float acc = 0.f, ss = 0.f;

    for (int base = start; base < end; base += 128) {
        int i = base + t;
        if (i < end) {
            int sc = g_col[i];
            float wv = __expf(lrelu(g_esrc2[sc] + ed));
            ss += wv;
            wbuf[t] = wv;
            scol[t] = sc;
        }
        __syncthreads();
        int cnt = min(128, end - base);
        int j = 0;
        for (; j + 3 < cnt; j += 4) {
            int s0 = scol[j], s1 = scol[j + 1], s2 = scol[j + 2], s3 = scol[j + 3];
            float w0 = wbuf[j], w1 = wbuf[j + 1], w2 = wbuf[j + 2], w3 = wbuf[j + 3];
            float v0 = g_h3[(size_t)s0 * C2 + t];
            float v1 = g_h3[(size_t)s1 * C2 + t];
            float v2 = g_h3[(size_t)s2 * C2 + t];
            float v3 = g_h3[(size_t)s3 * C2 + t];
            acc = fmaf(w0, v0, acc);
            acc = fmaf(w1, v1, acc);
            acc = fmaf(w2, v2, acc);
            acc = fmaf(w3, v3, acc);
        }
        for (; j < cnt; j++)
            acc = fmaf(wbuf[j], g_h3[(size_t)scol[j] * C2 + t], acc);
        __syncthreads();
    }

#pragma unroll
    for (int off = 16; off; off >>= 1) ss += __shfl_xor_sync(0xffffffffu, ss, off);
    if (lane == 0) sred[w] = ss;
    __syncthreads();
    float s = sred[0] + sred[1] + sred[2] + sred[3];
    float inv = (s > 0.f) ? 1.f / s : 0.f;
    out[(size_t)n * C2 + t] = acc * inv + b2[t];
}

// ---------------- launch ----------------
extern "C" void kernel_launch(void* const* d_in, const int* in_sizes, int n_in,
                              void* d_out, int out_size) {
    const float* x    = (const float*)d_in[0];
    const int*   ei   = (const int*)d_in[1];
    const float* sent = (const float*)d_in[2];
    const float* W1   = (const float*)d_in[3];
    const float* a1s  = (const float*)d_in[4];
    const float* a1d  = (const float*)d_in[5];
    const float* b1   = (const float*)d_in[6];
    const float* W2   = (const float*)d_in[7];
    const float* a2s  = (const float*)d_in[8];
    const float* a2d  = (const float*)d_in[9];
    const float* b2   = (const float*)d_in[10];
    float* out = (float*)d_out;

    int N = in_sizes[0] / SED;   // 20000
    int E = in_sizes[1] / 2;     // 320000
    int nb = (N + 511) / 512;    // scan blocks (<=64)

    float *p_h1, *p_act1, *p_h3, *p_c1;
    int *p_cnt;
    cudaGetSymbolAddress((void**)&p_h1,   g_h1);
    cudaGetSymbolAddress((void**)&p_act1, g_act1);
    cudaGetSymbolAddress((void**)&p_h3,   g_h3);
    cudaGetSymbolAddress((void**)&p_c1,   g_c1);
    cudaGetSymbolAddress((void**)&p_cnt,  g_cnt);

    // CSR build (dst-sorted)
    cudaMemsetAsync(p_cnt, 0, N * sizeof(int));
    k_count<<<(E + 255) / 256, 256>>>(ei, E);
    k_scan1<<<nb, 512>>>(N);
    k_scan3<<<(N + 255) / 256, 256>>>(N);
    k_scatter<<<(E + 255) / 256, 256>>>(ei, E);

    // Layer 1
    cudaMemsetAsync(p_c1, 0, HC1 * sizeof(float));
    k_constvec<<<dim3(4, 6), 128>>>(sent, W1);
    k_gemm_f16<<<dim3((N + 127) / 128, HC1 / 128), 256>>>(x, W1, p_h1, p_c1, N, HC1, SED);
    k_edot1<<<N, 128>>>(a1s, a1d);
    k_agg1<<<N, 128>>>(b1);

    // Layer 2
    k_gemm_f16<<<dim3((N + 127) / 128, C2 / 128), 256>>>(p_act1, W2, p_h3, nullptr, N, C2, HC1);
    k_edot2<<<(N + 3) / 4, 128>>>(a2s, a2d, N);
    k_agg2<<<N, 128>>>(b2, out);
}

// round 11
// speedup vs baseline: 1.2365x; 1.2365x over previous
#include <cuda_runtime.h>
#include <stdint.h>
#include <math.h>

// Problem constants (fixed shapes for this problem)
#define MAXN 20000
#define MAXE 320000
#define SED  768
#define HC1  512      // 4 heads * 128
#define C1   128
#define H1   4
#define C2   128

// ---------------- scratch (no allocation allowed; bss device globals) ----------------
__device__ __align__(16) float g_h1[MAXN * HC1];     // layer1 pre-attention features
__device__ __align__(16) float g_act1[MAXN * HC1];   // layer1 output after elu
__device__ __align__(16) float g_h3[MAXN * C2];      // layer2 pre-attention features
__device__ __align__(16) float g_esrc1[MAXN * 4];
__device__ __align__(16) float g_edst1[MAXN * 4];
__device__ float g_esrc2[MAXN];
__device__ float g_edst2[MAXN];
__device__ __align__(16) float g_c1[HC1];            // sent @ W1[768:] constant vector
__device__ int g_cnt[MAXN];
__device__ int g_rowptr[MAXN + 1];
__device__ int g_cursor[MAXN];
__device__ int g_col[MAXE];
__device__ int g_bsum[64];

__device__ __forceinline__ float lrelu(float x) { return x > 0.f ? x : 0.2f * x; }

__device__ __forceinline__ unsigned f2tf32(float f) {
    unsigned o;
    asm("cvt.rna.tf32.f32 %0, %1;" : "=r"(o) : "f"(f));
    return o;
}

// ---------------- CSR build ----------------
__global__ void k_count(const int* __restrict__ ei, int E) {
    int i = blockIdx.x * blockDim.x + threadIdx.x;
    if (i < E) atomicAdd(&g_cnt[ei[E + i]], 1);
}

__global__ void k_scan1(int N) {
    __shared__ int sm[512];
    int b = blockIdx.x, t = threadIdx.x, i = b * 512 + t;
    int v = (i < N) ? g_cnt[i] : 0;
    sm[t] = v;
    __syncthreads();
#pragma unroll
    for (int off = 1; off < 512; off <<= 1) {
        int u = (t >= off) ? sm[t - off] : 0;
        __syncthreads();
        sm[t] += u;
        __syncthreads();
    }
    if (i < N) g_rowptr[i + 1] = sm[t];
    if (t == 511) g_bsum[b] = sm[511];
}

// finalize rowptr + cursor; block offset = sum of g_bsum[0..blk-1] (blk constant per block)
__global__ void k_scan3(int N) {
    __shared__ int soff;
    int i = blockIdx.x * 256 + threadIdx.x;
    int blk = (blockIdx.x * 256) >> 9;
    if (threadIdx.x == 0) {
        int s = 0;
        for (int b = 0; b < blk; b++) s += g_bsum[b];
        soff = s;
    }
    __syncthreads();
    if (i < N) {
        int r = g_rowptr[i + 1] + soff;
        g_rowptr[i + 1] = r;
        g_cursor[i] = r - g_cnt[i];
    }
    if (i == 0) g_rowptr[0] = 0;
}

__global__ void k_scatter(const int* __restrict__ ei, int E) {
    int i = blockIdx.x * blockDim.x + threadIdx.x;
    if (i < E) {
        int dst = ei[E + i], src = ei[i];
        int pos = atomicAdd(&g_cursor[dst], 1);
        g_col[pos] = src;
    }
}

// ---------------- constant vector: c1 += sent @ W1[768:1536, :] (k-chunked, atomicAdd) ----
__global__ void k_constvec(const float* __restrict__ sent, const float* __restrict__ W1) {
    int j = blockIdx.x * 128 + threadIdx.x;
    int k0 = blockIdx.y * 128;
    float s = 0.f;
#pragma unroll 4
    for (int k = k0; k < k0 + 128; k++)
        s += sent[k] * W1[(size_t)(SED + k) * HC1 + j];
    atomicAdd(&g_c1[j], s);
}

// ---------------- TF32 tensor-core GEMM (double-buffered, register-staged, cvt.rna) ----
// Proven best (377.3us config). C[M,N] = A[M,K] @ B[K,N] (+ addv[col]).
// N % 128 == 0, K % 16 == 0; M bounds-checked.
#define LDA 24
#define LDB 132
__global__ __launch_bounds__(256, 2)
void k_gemm_tf32(const float* __restrict__ A, const float* __restrict__ B,
                 float* __restrict__ C, const float* __restrict__ addv,
                 int M, int N, int K) {
    __shared__ float As[2][128 * LDA];
    __shared__ float Bs[2][16 * LDB];

    int tid = threadIdx.x;
    int lane = tid & 31, wid = tid >> 5;
    int g = lane >> 2, t = lane & 3;
    int wm = (wid >> 2) * 64, wn = (wid & 3) * 32;
    int m0 = blockIdx.x * 128, n0 = blockIdx.y * 128;

    int a_row = tid >> 1;
    int a_k   = (tid & 1) * 4;
    int b_kr  = tid >> 5;
    int b_n   = (tid & 31) * 4;

    bool a_ok = (m0 + a_row) < M;
    const float* Aptr = A + (size_t)(m0 + a_row) * K;
    const float* Bptr = B + (size_t)n0;

    float acc[4][4][4];
#pragma unroll
    for (int mi = 0; mi < 4; mi++)
#pragma unroll
        for (int ni = 0; ni < 4; ni++)
#pragma unroll
            for (int c = 0; c < 4; c++) acc[mi][ni][c] = 0.f;

    float4 ra0, ra1, rb0, rb1;
    const float4 fz = make_float4(0.f, 0.f, 0.f, 0.f);

    {
        int kb = 0;
        ra0 = a_ok ? *(const float4*)&Aptr[kb + a_k]     : fz;
        ra1 = a_ok ? *(const float4*)&Aptr[kb + a_k + 8] : fz;
        rb0 = *(const float4*)&Bptr[(size_t)(kb + b_kr) * N + b_n];
        rb1 = *(const float4*)&Bptr[(size_t)(kb + b_kr + 8) * N + b_n];
        float* as = &As[0][a_row * LDA + a_k];
        as[0] = __uint_as_float(f2tf32(ra0.x)); as[1] = __uint_as_float(f2tf32(ra0.y));
        as[2] = __uint_as_float(f2tf32(ra0.z)); as[3] = __uint_as_float(f2tf32(ra0.w));
        as[8] = __uint_as_float(f2tf32(ra1.x)); as[9] = __uint_as_float(f2tf32(ra1.y));
        as[10] = __uint_as_float(f2tf32(ra1.z)); as[11] = __uint_as_float(f2tf32(ra1.w));
        float* bs0 = &Bs[0][b_kr * LDB + b_n];
        float* bs1 = &Bs[0][(b_kr + 8) * LDB + b_n];
        bs0[0] = __uint_as_float(f2tf32(rb0.x)); bs0[1] = __uint_as_float(f2tf32(rb0.y));
        bs0[2] = __uint_as_float(f2tf32(rb0.z)); bs0[3] = __uint_as_float(f2tf32(rb0.w));
        bs1[0] = __uint_as_float(f2tf32(rb1.x)); bs1[1] = __uint_as_float(f2tf32(rb1.y));
        bs1[2] = __uint_as_float(f2tf32(rb1.z)); bs1[3] = __uint_as_float(f2tf32(rb1.w));
    }
    __syncthreads();

    int nk = K / 16;
    for (int kt = 0; kt < nk; kt++) {
        int cur = kt & 1;
        if (kt + 1 < nk) {
            int kb = (kt + 1) * 16;
            ra0 = a_ok ? *(const float4*)&Aptr[kb + a_k]     : fz;
            ra1 = a_ok ? *(const float4*)&Aptr[kb + a_k + 8] : fz;
            rb0 = *(const float4*)&Bptr[(size_t)(kb + b_kr) * N + b_n];
            rb1 = *(const float4*)&Bptr[(size_t)(kb + b_kr + 8) * N + b_n];
        }

        const float* as = As[cur];
        const float* bs = Bs[cur];
#pragma unroll
        for (int ks = 0; ks < 2; ks++) {
            int kb = ks * 8;
            float2 af[4][2];
#pragma unroll
            for (int mi = 0; mi < 4; mi++) {
                int r = wm + mi * 16 + g;
                af[mi][0] = *(const float2*)&as[r * LDA + kb + 2 * t];
                af[mi][1] = *(const float2*)&as[(r + 8) * LDA + kb + 2 * t];
            }
#pragma unroll
            for (int ni = 0; ni < 4; ni++) {
                int cidx = wn + ni * 8 + g;
                unsigned b0 = __float_as_uint(bs[(kb + 2 * t) * LDB + cidx]);
                unsigned b1 = __float_as_uint(bs[(kb + 2 * t + 1) * LDB + cidx]);
#pragma unroll
                for (int mi = 0; mi < 4; mi++) {
                    unsigned a0 = __float_as_uint(af[mi][0].x);
                    unsigned a1 = __float_as_uint(af[mi][1].x);
                    unsigned a2 = __float_as_uint(af[mi][0].y);
                    unsigned a3 = __float_as_uint(af[mi][1].y);
                    asm volatile(
                        "mma.sync.aligned.m16n8k8.row.col.f32.tf32.tf32.f32 "
                        "{%0,%1,%2,%3}, {%4,%5,%6,%7}, {%8,%9}, {%0,%1,%2,%3};"
                        : "+f"(acc[mi][ni][0]), "+f"(acc[mi][ni][1]),
                          "+f"(acc[mi][ni][2]), "+f"(acc[mi][ni][3])
                        : "r"(a0), "r"(a1), "r"(a2), "r"(a3), "r"(b0), "r"(b1));
                }
            }
        }

        if (kt + 1 < nk) {
            int nxt = (kt + 1) & 1;
            float* asw = &As[nxt][a_row * LDA + a_k];
            asw[0] = __uint_as_float(f2tf32(ra0.x)); asw[1] = __uint_as_float(f2tf32(ra0.y));
            asw[2] = __uint_as_float(f2tf32(ra0.z)); asw[3] = __uint_as_float(f2tf32(ra0.w));
            asw[8] = __uint_as_float(f2tf32(ra1.x)); asw[9] = __uint_as_float(f2tf32(ra1.y));
            asw[10] = __uint_as_float(f2tf32(ra1.z)); asw[11] = __uint_as_float(f2tf32(ra1.w));
            float* bs0 = &Bs[nxt][b_kr * LDB + b_n];
            float* bs1 = &Bs[nxt][(b_kr + 8) * LDB + b_n];
            bs0[0] = __uint_as_float(f2tf32(rb0.x)); bs0[1] = __uint_as_float(f2tf32(rb0.y));
            bs0[2] = __uint_as_float(f2tf32(rb0.z)); bs0[3] = __uint_as_float(f2tf32(rb0.w));
            bs1[0] = __uint_as_float(f2tf32(rb1.x)); bs1[1] = __uint_as_float(f2tf32(rb1.y));
            bs1[2] = __uint_as_float(f2tf32(rb1.z)); bs1[3] = __uint_as_float(f2tf32(rb1.w));
            __syncthreads();
        }
    }

#pragma unroll
    for (int mi = 0; mi < 4; mi++) {
#pragma unroll
        for (int half = 0; half < 2; half++) {
            int r = m0 + wm + mi * 16 + g + half * 8;
            if (r < M) {
#pragma unroll
                for (int ni = 0; ni < 4; ni++) {
                    int c = n0 + wn + ni * 8 + 2 * t;
                    float2 v;
                    v.x = acc[mi][ni][half * 2 + 0];
                    v.y = acc[mi][ni][half * 2 + 1];
                    if (addv) { v.x += addv[c]; v.y += addv[c + 1]; }
                    *(float2*)&C[(size_t)r * N + c] = v;
                }
            }
        }
    }
}

// ---------------- attention dot products ----------------
__global__ void k_edot1(const float* __restrict__ a_src, const float* __restrict__ a_dst) {
    int n = blockIdx.x;
    int t = threadIdx.x, lane = t & 31, w = t >> 5;
    const float* hrow = &g_h1[(size_t)n * HC1 + w * C1];
    float s1 = 0.f, s2 = 0.f;
#pragma unroll
    for (int c = lane; c < C1; c += 32) {
        float v = hrow[c];
        s1 += v * a_src[w * C1 + c];
        s2 += v * a_dst[w * C1 + c];
    }
#pragma unroll
    for (int off = 16; off; off >>= 1) {
        s1 += __shfl_xor_sync(0xffffffffu, s1, off);
        s2 += __shfl_xor_sync(0xffffffffu, s2, off);
    }
    if (lane == 0) { g_esrc1[n * 4 + w] = s1; g_edst1[n * 4 + w] = s2; }
}

__global__ void k_edot2(const float* __restrict__ a_src, const float* __restrict__ a_dst, int N) {
    int t = threadIdx.x, lane = t & 31, w = t >> 5;
    int n = blockIdx.x * 4 + w;
    if (n >= N) return;
    const float* hrow = &g_h3[(size_t)n * C2];
    float s1 = 0.f, s2 = 0.f;
#pragma unroll
    for (int c = lane; c < C2; c += 32) {
        float v = hrow[c];
        s1 += v * a_src[c];
        s2 += v * a_dst[c];
    }
#pragma unroll
    for (int off = 16; off; off >>= 1) {
        s1 += __shfl_xor_sync(0xffffffffu, s1, off);
        s2 += __shfl_xor_sync(0xffffffffu, s2, off);
    }
    if (lane == 0) { g_esrc2[n] = s1; g_edst2[n] = s2; }
}

// ---------------- layer 1 aggregation: single-sweep normalization ----------------
__global__ void k_agg1(const float* __restrict__ b1) {
    int n = blockIdx.x;
    int t = threadIdx.x, lane = t & 31, w = t >> 5;
    int start = g_rowptr[n], end = g_rowptr[n + 1];
    float4 edv = *(const float4*)&g_edst1[n * 4];

    __shared__ float4 wbuf[128];
    __shared__ int scol[128];
    __shared__ float sred[4][4];

    float acc[4] = {0.f, 0.f, 0.f, 0.f};
    float ss[4]  = {0.f, 0.f, 0.f, 0.f};

    for (int base = start; base < end; base += 128) {
        int i = base + t;
        if (i < end) {
            int sc = g_col[i];
            float4 es = *(const float4*)&g_esrc1[sc * 4];
            float4 wv;
            wv.x = __expf(lrelu(es.x + edv.x));
            wv.y = __expf(lrelu(es.y + edv.y));
            wv.z = __expf(lrelu(es.z + edv.z));
            wv.w = __expf(lrelu(es.w + edv.w));
            ss[0] += wv.x; ss[1] += wv.y; ss[2] += wv.z; ss[3] += wv.w;
            wbuf[t] = wv;
            scol[t] = sc;
        }
        __syncthreads();
        int cnt = min(128, end - base);
        int j = 0;
        for (; j + 1 < cnt; j += 2) {
            int s0 = scol[j], s1 = scol[j + 1];
            float4 w0 = wbuf[j], w1 = wbuf[j + 1];
            const float* p0 = &g_h1[(size_t)s0 * HC1];
            const float* p1 = &g_h1[(size_t)s1 * HC1];
            float v00 = p0[t], v01 = p0[128 + t], v02 = p0[256 + t], v03 = p0[384 + t];
            float v10 = p1[t], v11 = p1[128 + t], v12 = p1[256 + t], v13 = p1[384 + t];
            acc[0] = fmaf(w0.x, v00, acc[0]);
            acc[1] = fmaf(w0.y, v01, acc[1]);
            acc[2] = fmaf(w0.z, v02, acc[2]);
            acc[3] = fmaf(w0.w, v03, acc[3]);
            acc[0] = fmaf(w1.x, v10, acc[0]);
            acc[1] = fmaf(w1.y, v11, acc[1]);
            acc[2] = fmaf(w1.z, v12, acc[2]);
            acc[3] = fmaf(w1.w, v13, acc[3]);
        }
        if (j < cnt) {
            int s0 = scol[j];
            float4 w0 = wbuf[j];
            const float* p0 = &g_h1[(size_t)s0 * HC1];
            acc[0] = fmaf(w0.x, p0[t],       acc[0]);
            acc[1] = fmaf(w0.y, p0[128 + t], acc[1]);
            acc[2] = fmaf(w0.z, p0[256 + t], acc[2]);
            acc[3] = fmaf(w0.w, p0[384 + t], acc[3]);
        }
        __syncthreads();
    }

#pragma unroll
    for (int h = 0; h < 4; h++)
#pragma unroll
        for (int off = 16; off; off >>= 1)
            ss[h] += __shfl_xor_sync(0xffffffffu, ss[h], off);
    if (lane == 0) { sred[0][w] = ss[0]; sred[1][w] = ss[1]; sred[2][w] = ss[2]; sred[3][w] = ss[3]; }
    __syncthreads();

    float* orow = &g_act1[(size_t)n * HC1];
#pragma unroll
    for (int h = 0; h < 4; h++) {
        float s = sred[h][0] + sred[h][1] + sred[h][2] + sred[h][3];
        float inv = (s > 0.f) ? 1.f / s : 0.f;   // deg-0 node -> out = bias
        float v = acc[h] * inv + b1[h * C1 + t];
        orow[h * C1 + t] = v > 0.f ? v : expm1f(v);
    }
}

// ---------------- layer 2 aggregation -> final output ----------------
__global__ void k_agg2(const float* __restrict__ b2, float* __restrict__ out) {
    int n = blockIdx.x;
    int t = threadIdx.x, lane = t & 31, w = t >> 5;
    int start = g_rowptr[n], end = g_rowptr[n + 1];
    float ed = g_edst2[n];

    __shared__ float wbuf[128];
    __shared__ int scol[128];
    __shared__ float sred[4];

    float acc = 0.f, ss = 0.f;

    for (int base = start; base < end; base += 128) {
        int i = base + t;
        if (i < end) {
            int sc = g_col[i];
            float wv = __expf(lrelu(g_esrc2[sc] + ed));
            ss += wv;
            wbuf[t] = wv;
            scol[t] = sc;
        }
        __syncthreads();
        int cnt = min(128, end - base);
        int j = 0;
        for (; j + 3 < cnt; j += 4) {
            int s0 = scol[j], s1 = scol[j + 1], s2 = scol[j + 2], s3 = scol[j + 3];
            float w0 = wbuf[j], w1 = wbuf[j + 1], w2 = wbuf[j + 2], w3 = wbuf[j + 3];
            float v0 = g_h3[(size_t)s0 * C2 + t];
            float v1 = g_h3[(size_t)s1 * C2 + t];
            float v2 = g_h3[(size_t)s2 * C2 + t];
            float v3 = g_h3[(size_t)s3 * C2 + t];
            acc = fmaf(w0, v0, acc);
            acc = fmaf(w1, v1, acc);
            acc = fmaf(w2, v2, acc);
            acc = fmaf(w3, v3, acc);
        }
        for (; j < cnt; j++)
            acc = fmaf(wbuf[j], g_h3[(size_t)scol[j] * C2 + t], acc);
        __syncthreads();
    }

#pragma unroll
    for (int off = 16; off; off >>= 1) ss += __shfl_xor_sync(0xffffffffu, ss, off);
    if (lane == 0) sred[w] = ss;
    __syncthreads();
    float s = sred[0] + sred[1] + sred[2] + sred[3];
    float inv = (s > 0.f) ? 1.f / s : 0.f;
    out[(size_t)n * C2 + t] = acc * inv + b2[t];
}

// ---------------- launch ----------------
extern "C" void kernel_launch(void* const* d_in, const int* in_sizes, int n_in,
                              void* d_out, int out_size) {
    const float* x    = (const float*)d_in[0];
    const int*   ei   = (const int*)d_in[1];
    const float* sent = (const float*)d_in[2];
    const float* W1   = (const float*)d_in[3];
    const float* a1s  = (const float*)d_in[4];
    const float* a1d  = (const float*)d_in[5];
    const float* b1   = (const float*)d_in[6];
    const float* W2   = (const float*)d_in[7];
    const float* a2s  = (const float*)d_in[8];
    const float* a2d  = (const float*)d_in[9];
    const float* b2   = (const float*)d_in[10];
    float* out = (float*)d_out;

    int N = in_sizes[0] / SED;   // 20000
    int E = in_sizes[1] / 2;     // 320000
    int nb = (N + 511) / 512;    // scan blocks (<=64)

    float *p_h1, *p_act1, *p_h3, *p_c1;
    int *p_cnt;
    cudaGetSymbolAddress((void**)&p_h1,   g_h1);
    cudaGetSymbolAddress((void**)&p_act1, g_act1);
    cudaGetSymbolAddress((void**)&p_h3,   g_h3);
    cudaGetSymbolAddress((void**)&p_c1,   g_c1);
    cudaGetSymbolAddress((void**)&p_cnt,  g_cnt);

    // CSR build (dst-sorted)
    cudaMemsetAsync(p_cnt, 0, N * sizeof(int));
    k_count<<<(E + 255) / 256, 256>>>(ei, E);
    k_scan1<<<nb, 512>>>(N);
    k_scan3<<<(N + 255) / 256, 256>>>(N);
    k_scatter<<<(E + 255) / 256, 256>>>(ei, E);

    // Layer 1
    cudaMemsetAsync(p_c1, 0, HC1 * sizeof(float));
    k_constvec<<<dim3(4, 6), 128>>>(sent, W1);
    k_gemm_tf32<<<dim3((N + 127) / 128, HC1 / 128), 256>>>(x, W1, p_h1, p_c1, N, HC1, SED);
    k_edot1<<<N, 128>>>(a1s, a1d);
    k_agg1<<<N, 128>>>(b1);

    // Layer 2
    k_gemm_tf32<<<dim3((N + 127) / 128, C2 / 128), 256>>>(p_act1, W2, p_h3, nullptr, N, C2, HC1);
    k_edot2<<<(N + 3) / 4, 128>>>(a2s, a2d, N);
    k_agg2<<<N, 128>>>(b2, out);
}

// round 16
// speedup vs baseline: 1.2989x; 1.0504x over previous
#include <cuda_runtime.h>
#include <cuda_fp16.h>
#include <stdint.h>
#include <math.h>

// Problem constants (fixed shapes for this problem)
#define MAXN 20000
#define MAXE 320000
#define SED  768
#define HC1  512      // 4 heads * 128
#define C1   128
#define H1   4
#define C2   128

// ---------------- scratch (no allocation allowed; bss device globals) ----------------
__device__ __align__(16) __half2 g_h1h[MAXN * 256];  // layer1 features, fp16 packed (512 ch)
__device__ __align__(16) __half2 g_h3h[MAXN * 64];   // layer2 features, fp16 packed (128 ch)
__device__ __align__(16) float g_act1[MAXN * HC1];   // layer1 output after elu (fp32, GEMM2 A)
__device__ __align__(16) float g_esrc1[MAXN * 4];
__device__ __align__(16) float g_edst1[MAXN * 4];
__device__ float g_esrc2[MAXN];
__device__ float g_edst2[MAXN];
__device__ __align__(16) float g_c1[HC1];            // sent @ W1[768:] constant vector
__device__ int g_cnt[MAXN];
__device__ int g_rowptr[MAXN + 1];
__device__ int g_cursor[MAXN];
__device__ int g_col[MAXE];
__device__ int g_bsum[64];

__device__ __forceinline__ float lrelu(float x) { return x > 0.f ? x : 0.2f * x; }

__device__ __forceinline__ unsigned f2tf32(float f) {
    unsigned o;
    asm("cvt.rna.tf32.f32 %0, %1;" : "=r"(o) : "f"(f));
    return o;
}

// ---------------- CSR build ----------------
__global__ void k_count(const int* __restrict__ ei, int E) {
    int i = blockIdx.x * blockDim.x + threadIdx.x;
    if (i < E) atomicAdd(&g_cnt[ei[E + i]], 1);
}

__global__ void k_scan1(int N) {
    __shared__ int sm[512];
    int b = blockIdx.x, t = threadIdx.x, i = b * 512 + t;
    int v = (i < N) ? g_cnt[i] : 0;
    sm[t] = v;
    __syncthreads();
#pragma unroll
    for (int off = 1; off < 512; off <<= 1) {
        int u = (t >= off) ? sm[t - off] : 0;
        __syncthreads();
        sm[t] += u;
        __syncthreads();
    }
    if (i < N) g_rowptr[i + 1] = sm[t];
    if (t == 511) g_bsum[b] = sm[511];
}

__global__ void k_scan3(int N) {
    __shared__ int soff;
    int i = blockIdx.x * 256 + threadIdx.x;
    int blk = (blockIdx.x * 256) >> 9;
    if (threadIdx.x == 0) {
        int s = 0;
        for (int b = 0; b < blk; b++) s += g_bsum[b];
        soff = s;
    }
    __syncthreads();
    if (i < N) {
        int r = g_rowptr[i + 1] + soff;
        g_rowptr[i + 1] = r;
        g_cursor[i] = r - g_cnt[i];
    }
    if (i == 0) g_rowptr[0] = 0;
}

__global__ void k_scatter(const int* __restrict__ ei, int E) {
    int i = blockIdx.x * blockDim.x + threadIdx.x;
    if (i < E) {
        int dst = ei[E + i], src = ei[i];
        int pos = atomicAdd(&g_cursor[dst], 1);
        g_col[pos] = src;
    }
}

// ---------------- constant vector: c1 += sent @ W1[768:1536, :] (k-chunked, atomicAdd) ----
__global__ void k_constvec(const float* __restrict__ sent, const float* __restrict__ W1) {
    int j = blockIdx.x * 128 + threadIdx.x;
    int k0 = blockIdx.y * 128;
    float s = 0.f;
#pragma unroll 4
    for (int k = k0; k < k0 + 128; k++)
        s += sent[k] * W1[(size_t)(SED + k) * HC1 + j];
    atomicAdd(&g_c1[j], s);
}

// ---------------- TF32 tensor-core GEMM -> fp16-packed output ----------------
// Ch[M, N/2] half2 = (A[M,K] @ B[K,N]) (+ addv[col]), computed fp32/tf32, stored fp16.
// N % 128 == 0, K % 16 == 0; M bounds-checked.
#define LDA 24
#define LDB 132
__global__ __launch_bounds__(256, 2)
void k_gemm_tf32(const float* __restrict__ A, const float* __restrict__ B,
                 __half2* __restrict__ Ch, const float* __restrict__ addv,
                 int M, int N, int K) {
    __shared__ float As[2][128 * LDA];
    __shared__ float Bs[2][16 * LDB];

    int tid = threadIdx.x;
    int lane = tid & 31, wid = tid >> 5;
    int g = lane >> 2, t = lane & 3;
    int wm = (wid >> 2) * 64, wn = (wid & 3) * 32;
    int m0 = blockIdx.x * 128, n0 = blockIdx.y * 128;

    int a_row = tid >> 1;
    int a_k   = (tid & 1) * 4;
    int b_kr  = tid >> 5;
    int b_n   = (tid & 31) * 4;

    bool a_ok = (m0 + a_row) < M;
    const float* Aptr = A + (size_t)(m0 + a_row) * K;
    const float* Bptr = B + (size_t)n0;

    float acc[4][4][4];
#pragma unroll
    for (int mi = 0; mi < 4; mi++)
#pragma unroll
        for (int ni = 0; ni < 4; ni++)
#pragma unroll
            for (int c = 0; c < 4; c++) acc[mi][ni][c] = 0.f;

    float4 ra0, ra1, rb0, rb1;
    const float4 fz = make_float4(0.f, 0.f, 0.f, 0.f);

    {
        int kb = 0;
        ra0 = a_ok ? *(const float4*)&Aptr[kb + a_k]     : fz;
        ra1 = a_ok ? *(const float4*)&Aptr[kb + a_k + 8] : fz;
        rb0 = *(const float4*)&Bptr[(size_t)(kb + b_kr) * N + b_n];
        rb1 = *(const float4*)&Bptr[(size_t)(kb + b_kr + 8) * N + b_n];
        float* as = &As[0][a_row * LDA + a_k];
        as[0] = __uint_as_float(f2tf32(ra0.x)); as[1] = __uint_as_float(f2tf32(ra0.y));
        as[2] = __uint_as_float(f2tf32(ra0.z)); as[3] = __uint_as_float(f2tf32(ra0.w));
        as[8] = __uint_as_float(f2tf32(ra1.x)); as[9] = __uint_as_float(f2tf32(ra1.y));
        as[10] = __uint_as_float(f2tf32(ra1.z)); as[11] = __uint_as_float(f2tf32(ra1.w));
        float* bs0 = &Bs[0][b_kr * LDB + b_n];
        float* bs1 = &Bs[0][(b_kr + 8) * LDB + b_n];
        bs0[0] = __uint_as_float(f2tf32(rb0.x)); bs0[1] = __uint_as_float(f2tf32(rb0.y));
        bs0[2] = __uint_as_float(f2tf32(rb0.z)); bs0[3] = __uint_as_float(f2tf32(rb0.w));
        bs1[0] = __uint_as_float(f2tf32(rb1.x)); bs1[1] = __uint_as_float(f2tf32(rb1.y));
        bs1[2] = __uint_as_float(f2tf32(rb1.z)); bs1[3] = __uint_as_float(f2tf32(rb1.w));
    }
    __syncthreads();

    int nk = K / 16;
    for (int kt = 0; kt < nk; kt++) {
        int cur = kt & 1;
        if (kt + 1 < nk) {
            int kb = (kt + 1) * 16;
            ra0 = a_ok ? *(const float4*)&Aptr[kb + a_k]     : fz;
            ra1 = a_ok ? *(const float4*)&Aptr[kb + a_k + 8] : fz;
            rb0 = *(const float4*)&Bptr[(size_t)(kb + b_kr) * N + b_n];
            rb1 = *(const float4*)&Bptr[(size_t)(kb + b_kr + 8) * N + b_n];
        }

        const float* as = As[cur];
        const float* bs = Bs[cur];
#pragma unroll
        for (int ks = 0; ks < 2; ks++) {
            int kb = ks * 8;
            float2 af[4][2];
#pragma unroll
            for (int mi = 0; mi < 4; mi++) {
                int r = wm + mi * 16 + g;
                af[mi][0] = *(const float2*)&as[r * LDA + kb + 2 * t];
                af[mi][1] = *(const float2*)&as[(r + 8) * LDA + kb + 2 * t];
            }
#pragma unroll
            for (int ni = 0; ni < 4; ni++) {
                int cidx = wn + ni * 8 + g;
                unsigned b0 = __float_as_uint(bs[(kb + 2 * t) * LDB + cidx]);
                unsigned b1 = __float_as_uint(bs[(kb + 2 * t + 1) * LDB + cidx]);
#pragma unroll
                for (int mi = 0; mi < 4; mi++) {
                    unsigned a0 = __float_as_uint(af[mi][0].x);
                    unsigned a1 = __float_as_uint(af[mi][1].x);
                    unsigned a2 = __float_as_uint(af[mi][0].y);
                    unsigned a3 = __float_as_uint(af[mi][1].y);
                    asm volatile(
                        "mma.sync.aligned.m16n8k8.row.col.f32.tf32.tf32.f32 "
                        "{%0,%1,%2,%3}, {%4,%5,%6,%7}, {%8,%9}, {%0,%1,%2,%3};"
                        : "+f"(acc[mi][ni][0]), "+f"(acc[mi][ni][1]),
                          "+f"(acc[mi][ni][2]), "+f"(acc[mi][ni][3])
                        : "r"(a0), "r"(a1), "r"(a2), "r"(a3), "r"(b0), "r"(b1));
                }
            }
        }

        if (kt + 1 < nk) {
            int nxt = (kt + 1) & 1;
            float* asw = &As[nxt][a_row * LDA + a_k];
            asw[0] = __uint_as_float(f2tf32(ra0.x)); asw[1] = __uint_as_float(f2tf32(ra0.y));
            asw[2] = __uint_as_float(f2tf32(ra0.z)); asw[3] = __uint_as_float(f2tf32(ra0.w));
            asw[8] = __uint_as_float(f2tf32(ra1.x)); asw[9] = __uint_as_float(f2tf32(ra1.y));
            asw[10] = __uint_as_float(f2tf32(ra1.z)); asw[11] = __uint_as_float(f2tf32(ra1.w));
            float* bs0 = &Bs[nxt][b_kr * LDB + b_n];
            float* bs1 = &Bs[nxt][(b_kr + 8) * LDB + b_n];
            bs0[0] = __uint_as_float(f2tf32(rb0.x)); bs0[1] = __uint_as_float(f2tf32(rb0.y));
            bs0[2] = __uint_as_float(f2tf32(rb0.z)); bs0[3] = __uint_as_float(f2tf32(rb0.w));
            bs1[0] = __uint_as_float(f2tf32(rb1.x)); bs1[1] = __uint_as_float(f2tf32(rb1.y));
            bs1[2] = __uint_as_float(f2tf32(rb1.z)); bs1[3] = __uint_as_float(f2tf32(rb1.w));
            __syncthreads();
        }
    }

    int halfN = N >> 1;
#pragma unroll
    for (int mi = 0; mi < 4; mi++) {
#pragma unroll
        for (int half = 0; half < 2; half++) {
            int r = m0 + wm + mi * 16 + g + half * 8;
            if (r < M) {
#pragma unroll
                for (int ni = 0; ni < 4; ni++) {
                    int c = n0 + wn + ni * 8 + 2 * t;
                    float vx = acc[mi][ni][half * 2 + 0];
                    float vy = acc[mi][ni][half * 2 + 1];
                    if (addv) { vx += addv[c]; vy += addv[c + 1]; }
                    Ch[(size_t)r * halfN + (c >> 1)] = __floats2half2_rn(vx, vy);
                }
            }
        }
    }
}

// ---------------- attention dot products (fp16 inputs) ----------------
__global__ void k_edot1(const float* __restrict__ a_src, const float* __restrict__ a_dst) {
    int n = blockIdx.x;
    int t = threadIdx.x, lane = t & 31, w = t >> 5;   // warp w = head w
    const __half2* row = &g_h1h[(size_t)n * 256 + w * 64];
    const float* asv = a_src + w * C1;
    const float* adv = a_dst + w * C1;
    float s1 = 0.f, s2 = 0.f;
#pragma unroll
    for (int i = lane; i < 64; i += 32) {
        float2 v = __half22float2(row[i]);
        int c = 2 * i;
        s1 += v.x * asv[c] + v.y * asv[c + 1];
        s2 += v.x * adv[c] + v.y * adv[c + 1];
    }
#pragma unroll
    for (int off = 16; off; off >>= 1) {
        s1 += __shfl_xor_sync(0xffffffffu, s1, off);
        s2 += __shfl_xor_sync(0xffffffffu, s2, off);
    }
    if (lane == 0) { g_esrc1[n * 4 + w] = s1; g_edst1[n * 4 + w] = s2; }
}

__global__ void k_edot2(const float* __restrict__ a_src, const float* __restrict__ a_dst, int N) {
    int t = threadIdx.x, lane = t & 31, w = t >> 5;
    int n = blockIdx.x * 4 + w;
    if (n >= N) return;
    const __half2* row = &g_h3h[(size_t)n * 64];
    float s1 = 0.f, s2 = 0.f;
#pragma unroll
    for (int i = lane; i < 64; i += 32) {
        float2 v = __half22float2(row[i]);
        int c = 2 * i;
        s1 += v.x * a_src[c] + v.y * a_src[c + 1];
        s2 += v.x * a_dst[c] + v.y * a_dst[c + 1];
    }
#pragma unroll
    for (int off = 16; off; off >>= 1) {
        s1 += __shfl_xor_sync(0xffffffffu, s1, off);
        s2 += __shfl_xor_sync(0xffffffffu, s2, off);
    }
    if (lane == 0) { g_esrc2[n] = s1; g_edst2[n] = s2; }
}

// ---------------- layer 1 aggregation (fp16 gather, fp32 accumulate) ----------------
// Thread t owns half2 words {t, 128+t} of the 256-word row:
//   word t     -> channels 2t, 2t+1       -> head h0 = t>>6
//   word 128+t -> channels 256+2t, ...    -> head h1 = 2 + h0
__global__ void k_agg1(const float* __restrict__ b1) {
    int n = blockIdx.x;
    int t = threadIdx.x, lane = t & 31, w = t >> 5;
    int start = g_rowptr[n], end = g_rowptr[n + 1];
    float4 edv = *(const float4*)&g_edst1[n * 4];
    int h0 = t >> 6, h1 = 2 + h0;

    __shared__ float wbuf[128][4];
    __shared__ int scol[128];
    __shared__ float sred[4][4];

    float2 accA = make_float2(0.f, 0.f);
    float2 accB = make_float2(0.f, 0.f);
    float ss[4] = {0.f, 0.f, 0.f, 0.f};

    for (int base = start; base < end; base += 128) {
        int i = base + t;
        if (i < end) {
            int sc = g_col[i];
            float4 es = *(const float4*)&g_esrc1[sc * 4];
            float w0 = __expf(lrelu(es.x + edv.x));
            float w1 = __expf(lrelu(es.y + edv.y));
            float w2 = __expf(lrelu(es.z + edv.z));
            float w3 = __expf(lrelu(es.w + edv.w));
            ss[0] += w0; ss[1] += w1; ss[2] += w2; ss[3] += w3;
            wbuf[t][0] = w0; wbuf[t][1] = w1; wbuf[t][2] = w2; wbuf[t][3] = w3;
            scol[t] = sc;
        }
        __syncthreads();
        int cnt = min(128, end - base);
        int j = 0;
        for (; j + 1 < cnt; j += 2) {
            const __half2* p0 = &g_h1h[(size_t)scol[j] * 256];
            const __half2* p1 = &g_h1h[(size_t)scol[j + 1] * 256];
            float wa0 = wbuf[j][h0],     wb0 = wbuf[j][h1];
            float wa1 = wbuf[j + 1][h0], wb1 = wbuf[j + 1][h1];
            float2 a0 = __half22float2(p0[t]);
            float2 b0 = __half22float2(p0[128 + t]);
            float2 a1 = __half22float2(p1[t]);
            float2 b1v = __half22float2(p1[128 + t]);
            accA.x = fmaf(wa0, a0.x, accA.x); accA.y = fmaf(wa0, a0.y, accA.y);
            accB.x = fmaf(wb0, b0.x, accB.x); accB.y = fmaf(wb0, b0.y, accB.y);
            accA.x = fmaf(wa1, a1.x, accA.x); accA.y = fmaf(wa1, a1.y, accA.y);
            accB.x = fmaf(wb1, b1v.x, accB.x); accB.y = fmaf(wb1, b1v.y, accB.y);
        }
        if (j < cnt) {
            const __half2* p0 = &g_h1h[(size_t)scol[j] * 256];
            float wa0 = wbuf[j][h0], wb0 = wbuf[j][h1];
            float2 a0 = __half22float2(p0[t]);
            float2 b0 = __half22float2(p0[128 + t]);
            accA.x = fmaf(wa0, a0.x, accA.x); accA.y = fmaf(wa0, a0.y, accA.y);
            accB.x = fmaf(wb0, b0.x, accB.x); accB.y = fmaf(wb0, b0.y, accB.y);
        }
        __syncthreads();
    }

    // block-reduce denominators
#pragma unroll
    for (int h = 0; h < 4; h++)
#pragma unroll
        for (int off = 16; off; off >>= 1)
            ss[h] += __shfl_xor_sync(0xffffffffu, ss[h], off);
    if (lane == 0) { sred[0][w] = ss[0]; sred[1][w] = ss[1]; sred[2][w] = ss[2]; sred[3][w] = ss[3]; }
    __syncthreads();

    float inv[4];
#pragma unroll
    for (int h = 0; h < 4; h++) {
        float s = sred[h][0] + sred[h][1] + sred[h][2] + sred[h][3];
        inv[h] = (s > 0.f) ? 1.f / s : 0.f;   // deg-0 node -> out = bias
    }

    float* orow = &g_act1[(size_t)n * HC1];
    {
        float2 bv = *(const float2*)&b1[2 * t];
        float ox = accA.x * inv[h0] + bv.x;
        float oy = accA.y * inv[h0] + bv.y;
        ox = ox > 0.f ? ox : expm1f(ox);
        oy = oy > 0.f ? oy : expm1f(oy);
        *(float2*)&orow[2 * t] = make_float2(ox, oy);
    }
    {
        float2 bv = *(const float2*)&b1[256 + 2 * t];
        float ox = accB.x * inv[h1] + bv.x;
        float oy = accB.y * inv[h1] + bv.y;
        ox = ox > 0.f ? ox : expm1f(ox);
        oy = oy > 0.f ? oy : expm1f(oy);
        *(float2*)&orow[256 + 2 * t] = make_float2(ox, oy);
    }
}

// ---------------- layer 2 aggregation (fp16 gather) -> final output ----------------
// 128 threads = 2 edge-subgroups x 64 words; cross-subgroup reduce at the end.
__global__ void k_agg2(const float* __restrict__ b2, float* __restrict__ out) {
    int n = blockIdx.x;
    int t = threadIdx.x, lane = t & 31, w = t >> 5;
    int sub = t >> 6, tw = t & 63;
    int start = g_rowptr[n], end = g_rowptr[n + 1];
    float ed = g_edst2[n];

    __shared__ float wbuf[128];
    __shared__ int scol[128];
    __shared__ float sred[4];
    __shared__ float2 sacc[128];

    float2 acc = make_float2(0.f, 0.f);
    float ss = 0.f;

    for (int base = start; base < end; base += 128) {
        int i = base + t;
        if (i < end) {
            int sc = g_col[i];
            float wv = __expf(lrelu(g_esrc2[sc] + ed));
            ss += wv;
            wbuf[t] = wv;
            scol[t] = sc;
        }
        __syncthreads();
        int cnt = min(128, end - base);
        for (int j = sub; j < cnt; j += 2) {
            const __half2* p = &g_h3h[(size_t)scol[j] * 64];
            float wv = wbuf[j];
            float2 v = __half22float2(p[tw]);
            acc.x = fmaf(wv, v.x, acc.x);
            acc.y = fmaf(wv, v.y, acc.y);
        }
        __syncthreads();
    }

#pragma unroll
    for (int off = 16; off; off >>= 1) ss += __shfl_xor_sync(0xffffffffu, ss, off);
    if (lane == 0) sred[w] = ss;
    sacc[t] = acc;
    __syncthreads();

    if (t < 64) {
        float s = sred[0] + sred[1] + sred[2] + sred[3];
        float inv = (s > 0.f) ? 1.f / s : 0.f;
        float2 a0 = sacc[t], a1 = sacc[64 + t];
        float2 bv = *(const float2*)&b2[2 * t];
        float ox = (a0.x + a1.x) * inv + bv.x;
        float oy = (a0.y + a1.y) * inv + bv.y;
        *(float2*)&out[(size_t)n * C2 + 2 * t] = make_float2(ox, oy);
    }
}

// ---------------- launch ----------------
extern "C" void kernel_launch(void* const* d_in, const int* in_sizes, int n_in,
                              void* d_out, int out_size) {
    const float* x    = (const float*)d_in[0];
    const int*   ei   = (const int*)d_in[1];
    const float* sent = (const float*)d_in[2];
    const float* W1   = (const float*)d_in[3];
    const float* a1s  = (const float*)d_in[4];
    const float* a1d  = (const float*)d_in[5];
    const float* b1   = (const float*)d_in[6];
    const float* W2   = (const float*)d_in[7];
    const float* a2s  = (const float*)d_in[8];
    const float* a2d  = (const float*)d_in[9];
    const float* b2   = (const float*)d_in[10];
    float* out = (float*)d_out;

    int N = in_sizes[0] / SED;   // 20000
    int E = in_sizes[1] / 2;     // 320000
    int nb = (N + 511) / 512;    // scan blocks (<=64)

    float *p_act1, *p_c1;
    __half2 *p_h1h, *p_h3h;
    int *p_cnt;
    cudaGetSymbolAddress((void**)&p_h1h,  g_h1h);
    cudaGetSymbolAddress((void**)&p_h3h,  g_h3h);
    cudaGetSymbolAddress((void**)&p_act1, g_act1);
    cudaGetSymbolAddress((void**)&p_c1,   g_c1);
    cudaGetSymbolAddress((void**)&p_cnt,  g_cnt);

    // CSR build (dst-sorted)
    cudaMemsetAsync(p_cnt, 0, N * sizeof(int));
    k_count<<<(E + 255) / 256, 256>>>(ei, E);
    k_scan1<<<nb, 512>>>(N);
    k_scan3<<<(N + 255) / 256, 256>>>(N);
    k_scatter<<<(E + 255) / 256, 256>>>(ei, E);

    // Layer 1
    cudaMemsetAsync(p_c1, 0, HC1 * sizeof(float));
    k_constvec<<<dim3(4, 6), 128>>>(sent, W1);
    k_gemm_tf32<<<dim3((N + 127) / 128, HC1 / 128), 256>>>(x, W1, p_h1h, p_c1, N, HC1, SED);
    k_edot1<<<N, 128>>>(a1s, a1d);
    k_agg1<<<N, 128>>>(b1);

    // Layer 2
    k_gemm_tf32<<<dim3((N + 127) / 128, C2 / 128), 256>>>(p_act1, W2, p_h3h, nullptr, N, C2, HC1);
    k_edot2<<<(N + 3) / 4, 128>>>(a2s, a2d, N);
    k_agg2<<<N, 128>>>(b2, out);
}

// round 17
// speedup vs baseline: 1.3550x; 1.0432x over previous
#include <cuda_runtime.h>
#include <cuda_fp16.h>
#include <stdint.h>
#include <math.h>

// Problem constants (fixed shapes for this problem)
#define MAXN 20000
#define MAXE 320000
#define SED  768
#define HC1  512      // 4 heads * 128
#define C1   128
#define H1   4
#define C2   128

// ---------------- scratch (no allocation allowed; bss device globals) ----------------
__device__ __align__(16) __half2 g_h1h[MAXN * 256];  // layer1 features, fp16 packed (512 ch)
__device__ __align__(16) __half2 g_h3h[MAXN * 64];   // layer2 features, fp16 packed (128 ch)
__device__ __align__(16) float g_act1[MAXN * HC1];   // layer1 output after elu (fp32, GEMM2 A)
__device__ __align__(16) float g_esrc1[MAXN * 4];
__device__ __align__(16) float g_edst1[MAXN * 4];
__device__ float g_esrc2[MAXN];
__device__ float g_edst2[MAXN];
__device__ __align__(16) float g_c1[HC1];            // sent @ W1[768:] constant vector
__device__ int g_cnt[MAXN];
__device__ int g_rowptr[MAXN + 1];
__device__ int g_cursor[MAXN];
__device__ int g_col[MAXE];
__device__ int g_bsum[64];

__device__ __forceinline__ float lrelu(float x) { return x > 0.f ? x : 0.2f * x; }

__device__ __forceinline__ unsigned f2tf32(float f) {
    unsigned o;
    asm("cvt.rna.tf32.f32 %0, %1;" : "=r"(o) : "f"(f));
    return o;
}

// ---------------- CSR build ----------------
__global__ void k_count(const int* __restrict__ ei, int E) {
    int i = blockIdx.x * blockDim.x + threadIdx.x;
    if (i < E) atomicAdd(&g_cnt[ei[E + i]], 1);
}

__global__ void k_scan1(int N) {
    __shared__ int sm[512];
    int b = blockIdx.x, t = threadIdx.x, i = b * 512 + t;
    int v = (i < N) ? g_cnt[i] : 0;
    sm[t] = v;
    __syncthreads();
#pragma unroll
    for (int off = 1; off < 512; off <<= 1) {
        int u = (t >= off) ? sm[t - off] : 0;
        __syncthreads();
        sm[t] += u;
        __syncthreads();
    }
    if (i < N) g_rowptr[i + 1] = sm[t];
    if (t == 511) g_bsum[b] = sm[511];
}

__global__ void k_scan3(int N) {
    __shared__ int soff;
    int i = blockIdx.x * 256 + threadIdx.x;
    int blk = (blockIdx.x * 256) >> 9;
    if (threadIdx.x == 0) {
        int s = 0;
        for (int b = 0; b < blk; b++) s += g_bsum[b];
        soff = s;
    }
    __syncthreads();
    if (i < N) {
        int r = g_rowptr[i + 1] + soff;
        g_rowptr[i + 1] = r;
        g_cursor[i] = r - g_cnt[i];
    }
    if (i == 0) g_rowptr[0] = 0;
}

__global__ void k_scatter(const int* __restrict__ ei, int E) {
    int i = blockIdx.x * blockDim.x + threadIdx.x;
    if (i < E) {
        int dst = ei[E + i], src = ei[i];
        int pos = atomicAdd(&g_cursor[dst], 1);
        g_col[pos] = src;
    }
}

// ---------------- constant vector: c1 += sent @ W1[768:1536, :] (k-chunked, atomicAdd) ----
__global__ void k_constvec(const float* __restrict__ sent, const float* __restrict__ W1) {
    int j = blockIdx.x * 128 + threadIdx.x;
    int k0 = blockIdx.y * 128;
    float s = 0.f;
#pragma unroll 4
    for (int k = k0; k < k0 + 128; k++)
        s += sent[k] * W1[(size_t)(SED + k) * HC1 + j];
    atomicAdd(&g_c1[j], s);
}

// ---------------- TF32 tensor-core GEMM -> fp16-packed output ----------------
// Ch[M, N/2] half2 = (A[M,K] @ B[K,N]) (+ addv[col]), computed fp32/tf32, stored fp16.
// N % 128 == 0, K % 16 == 0; M bounds-checked.
#define LDA 24
#define LDB 132
__global__ __launch_bounds__(256, 2)
void k_gemm_tf32(const float* __restrict__ A, const float* __restrict__ B,
                 __half2* __restrict__ Ch, const float* __restrict__ addv,
                 int M, int N, int K) {
    __shared__ float As[2][128 * LDA];
    __shared__ float Bs[2][16 * LDB];

    int tid = threadIdx.x;
    int lane = tid & 31, wid = tid >> 5;
    int g = lane >> 2, t = lane & 3;
    int wm = (wid >> 2) * 64, wn = (wid & 3) * 32;
    int m0 = blockIdx.x * 128, n0 = blockIdx.y * 128;

    int a_row = tid >> 1;
    int a_k   = (tid & 1) * 4;
    int b_kr  = tid >> 5;
    int b_n   = (tid & 31) * 4;

    bool a_ok = (m0 + a_row) < M;
    const float* Aptr = A + (size_t)(m0 + a_row) * K;
    const float* Bptr = B + (size_t)n0;

    float acc[4][4][4];
#pragma unroll
    for (int mi = 0; mi < 4; mi++)
#pragma unroll
        for (int ni = 0; ni < 4; ni++)
#pragma unroll
            for (int c = 0; c < 4; c++) acc[mi][ni][c] = 0.f;

    float4 ra0, ra1, rb0, rb1;
    const float4 fz = make_float4(0.f, 0.f, 0.f, 0.f);

    {
        int kb = 0;
        ra0 = a_ok ? *(const float4*)&Aptr[kb + a_k]     : fz;
        ra1 = a_ok ? *(const float4*)&Aptr[kb + a_k + 8] : fz;
        rb0 = *(const float4*)&Bptr[(size_t)(kb + b_kr) * N + b_n];
        rb1 = *(const float4*)&Bptr[(size_t)(kb + b_kr + 8) * N + b_n];
        float* as = &As[0][a_row * LDA + a_k];
        as[0] = __uint_as_float(f2tf32(ra0.x)); as[1] = __uint_as_float(f2tf32(ra0.y));
        as[2] = __uint_as_float(f2tf32(ra0.z)); as[3] = __uint_as_float(f2tf32(ra0.w));
        as[8] = __uint_as_float(f2tf32(ra1.x)); as[9] = __uint_as_float(f2tf32(ra1.y));
        as[10] = __uint_as_float(f2tf32(ra1.z)); as[11] = __uint_as_float(f2tf32(ra1.w));
        float* bs0 = &Bs[0][b_kr * LDB + b_n];
        float* bs1 = &Bs[0][(b_kr + 8) * LDB + b_n];
        bs0[0] = __uint_as_float(f2tf32(rb0.x)); bs0[1] = __uint_as_float(f2tf32(rb0.y));
        bs0[2] = __uint_as_float(f2tf32(rb0.z)); bs0[3] = __uint_as_float(f2tf32(rb0.w));
        bs1[0] = __uint_as_float(f2tf32(rb1.x)); bs1[1] = __uint_as_float(f2tf32(rb1.y));
        bs1[2] = __uint_as_float(f2tf32(rb1.z)); bs1[3] = __uint_as_float(f2tf32(rb1.w));
    }
    __syncthreads();

    int nk = K / 16;
    for (int kt = 0; kt < nk; kt++) {
        int cur = kt & 1;
        if (kt + 1 < nk) {
            int kb = (kt + 1) * 16;
            ra0 = a_ok ? *(const float4*)&Aptr[kb + a_k]     : fz;
            ra1 = a_ok ? *(const float4*)&Aptr[kb + a_k + 8] : fz;
            rb0 = *(const float4*)&Bptr[(size_t)(kb + b_kr) * N + b_n];
            rb1 = *(const float4*)&Bptr[(size_t)(kb + b_kr + 8) * N + b_n];
        }

        const float* as = As[cur];
        const float* bs = Bs[cur];
#pragma unroll
        for (int ks = 0; ks < 2; ks++) {
            int kb = ks * 8;
            float2 af[4][2];
#pragma unroll
            for (int mi = 0; mi < 4; mi++) {
                int r = wm + mi * 16 + g;
                af[mi][0] = *(const float2*)&as[r * LDA + kb + 2 * t];
                af[mi][1] = *(const float2*)&as[(r + 8) * LDA + kb + 2 * t];
            }
#pragma unroll
            for (int ni = 0; ni < 4; ni++) {
                int cidx = wn + ni * 8 + g;
                unsigned b0 = __float_as_uint(bs[(kb + 2 * t) * LDB + cidx]);
                unsigned b1 = __float_as_uint(bs[(kb + 2 * t + 1) * LDB + cidx]);
#pragma unroll
                for (int mi = 0; mi < 4; mi++) {
                    unsigned a0 = __float_as_uint(af[mi][0].x);
                    unsigned a1 = __float_as_uint(af[mi][1].x);
                    unsigned a2 = __float_as_uint(af[mi][0].y);
                    unsigned a3 = __float_as_uint(af[mi][1].y);
                    asm volatile(
                        "mma.sync.aligned.m16n8k8.row.col.f32.tf32.tf32.f32 "
                        "{%0,%1,%2,%3}, {%4,%5,%6,%7}, {%8,%9}, {%0,%1,%2,%3};"
                        : "+f"(acc[mi][ni][0]), "+f"(acc[mi][ni][1]),
                          "+f"(acc[mi][ni][2]), "+f"(acc[mi][ni][3])
                        : "r"(a0), "r"(a1), "r"(a2), "r"(a3), "r"(b0), "r"(b1));
                }
            }
        }

        if (kt + 1 < nk) {
            int nxt = (kt + 1) & 1;
            float* asw = &As[nxt][a_row * LDA + a_k];
            asw[0] = __uint_as_float(f2tf32(ra0.x)); asw[1] = __uint_as_float(f2tf32(ra0.y));
            asw[2] = __uint_as_float(f2tf32(ra0.z)); asw[3] = __uint_as_float(f2tf32(ra0.w));
            asw[8] = __uint_as_float(f2tf32(ra1.x)); asw[9] = __uint_as_float(f2tf32(ra1.y));
            asw[10] = __uint_as_float(f2tf32(ra1.z)); asw[11] = __uint_as_float(f2tf32(ra1.w));
            float* bs0 = &Bs[nxt][b_kr * LDB + b_n];
            float* bs1 = &Bs[nxt][(b_kr + 8) * LDB + b_n];
            bs0[0] = __uint_as_float(f2tf32(rb0.x)); bs0[1] = __uint_as_float(f2tf32(rb0.y));
            bs0[2] = __uint_as_float(f2tf32(rb0.z)); bs0[3] = __uint_as_float(f2tf32(rb0.w));
            bs1[0] = __uint_as_float(f2tf32(rb1.x)); bs1[1] = __uint_as_float(f2tf32(rb1.y));
            bs1[2] = __uint_as_float(f2tf32(rb1.z)); bs1[3] = __uint_as_float(f2tf32(rb1.w));
            __syncthreads();
        }
    }

    int halfN = N >> 1;
#pragma unroll
    for (int mi = 0; mi < 4; mi++) {
#pragma unroll
        for (int half = 0; half < 2; half++) {
            int r = m0 + wm + mi * 16 + g + half * 8;
            if (r < M) {
#pragma unroll
                for (int ni = 0; ni < 4; ni++) {
                    int c = n0 + wn + ni * 8 + 2 * t;
                    float vx = acc[mi][ni][half * 2 + 0];
                    float vy = acc[mi][ni][half * 2 + 1];
                    if (addv) { vx += addv[c]; vy += addv[c + 1]; }
                    Ch[(size_t)r * halfN + (c >> 1)] = __floats2half2_rn(vx, vy);
                }
            }
        }
    }
}

// ---------------- attention dot products (fp16 inputs) ----------------
__global__ void k_edot1(const float* __restrict__ a_src, const float* __restrict__ a_dst) {
    int n = blockIdx.x;
    int t = threadIdx.x, lane = t & 31, w = t >> 5;   // warp w = head w
    const __half2* row = &g_h1h[(size_t)n * 256 + w * 64];
    const float* asv = a_src + w * C1;
    const float* adv = a_dst + w * C1;
    float s1 = 0.f, s2 = 0.f;
#pragma unroll
    for (int i = lane; i < 64; i += 32) {
        float2 v = __half22float2(row[i]);
        int c = 2 * i;
        s1 += v.x * asv[c] + v.y * asv[c + 1];
        s2 += v.x * adv[c] + v.y * adv[c + 1];
    }
#pragma unroll
    for (int off = 16; off; off >>= 1) {
        s1 += __shfl_xor_sync(0xffffffffu, s1, off);
        s2 += __shfl_xor_sync(0xffffffffu, s2, off);
    }
    if (lane == 0) { g_esrc1[n * 4 + w] = s1; g_edst1[n * 4 + w] = s2; }
}

__global__ void k_edot2(const float* __restrict__ a_src, const float* __restrict__ a_dst, int N) {
    int t = threadIdx.x, lane = t & 31, w = t >> 5;
    int n = blockIdx.x * 4 + w;
    if (n >= N) return;
    const __half2* row = &g_h3h[(size_t)n * 64];
    float s1 = 0.f, s2 = 0.f;
#pragma unroll
    for (int i = lane; i < 64; i += 32) {
        float2 v = __half22float2(row[i]);
        int c = 2 * i;
        s1 += v.x * a_src[c] + v.y * a_src[c + 1];
        s2 += v.x * a_dst[c] + v.y * a_dst[c + 1];
    }
#pragma unroll
    for (int off = 16; off; off >>= 1) {
        s1 += __shfl_xor_sync(0xffffffffu, s1, off);
        s2 += __shfl_xor_sync(0xffffffffu, s2, off);
    }
    if (lane == 0) { g_esrc2[n] = s1; g_edst2[n] = s2; }
}

// ---------------- layer 1 aggregation (fp16 gather, fp32 accumulate) ----------------
__global__ void k_agg1(const float* __restrict__ b1) {
    int n = blockIdx.x;
    int t = threadIdx.x, lane = t & 31, w = t >> 5;
    int start = g_rowptr[n], end = g_rowptr[n + 1];
    float4 edv = *(const float4*)&g_edst1[n * 4];
    int h0 = t >> 6, h1 = 2 + h0;

    __shared__ float wbuf[128][4];
    __shared__ int scol[128];
    __shared__ float sred[4][4];

    float2 accA = make_float2(0.f, 0.f);
    float2 accB = make_float2(0.f, 0.f);
    float ss[4] = {0.f, 0.f, 0.f, 0.f};

    for (int base = start; base < end; base += 128) {
        int i = base + t;
        if (i < end) {
            int sc = g_col[i];
            float4 es = *(const float4*)&g_esrc1[sc * 4];
            float w0 = __expf(lrelu(es.x + edv.x));
            float w1 = __expf(lrelu(es.y + edv.y));
            float w2 = __expf(lrelu(es.z + edv.z));
            float w3 = __expf(lrelu(es.w + edv.w));
            ss[0] += w0; ss[1] += w1; ss[2] += w2; ss[3] += w3;
            wbuf[t][0] = w0; wbuf[t][1] = w1; wbuf[t][2] = w2; wbuf[t][3] = w3;
            scol[t] = sc;
        }
        __syncthreads();
        int cnt = min(128, end - base);
        int j = 0;
        for (; j + 1 < cnt; j += 2) {
            const __half2* p0 = &g_h1h[(size_t)scol[j] * 256];
            const __half2* p1 = &g_h1h[(size_t)scol[j + 1] * 256];
            float wa0 = wbuf[j][h0],     wb0 = wbuf[j][h1];
            float wa1 = wbuf[j + 1][h0], wb1 = wbuf[j + 1][h1];
            float2 a0 = __half22float2(p0[t]);
            float2 b0 = __half22float2(p0[128 + t]);
            float2 a1 = __half22float2(p1[t]);
            float2 b1v = __half22float2(p1[128 + t]);
            accA.x = fmaf(wa0, a0.x, accA.x); accA.y = fmaf(wa0, a0.y, accA.y);
            accB.x = fmaf(wb0, b0.x, accB.x); accB.y = fmaf(wb0, b0.y, accB.y);
            accA.x = fmaf(wa1, a1.x, accA.x); accA.y = fmaf(wa1, a1.y, accA.y);
            accB.x = fmaf(wb1, b1v.x, accB.x); accB.y = fmaf(wb1, b1v.y, accB.y);
        }
        if (j < cnt) {
            const __half2* p0 = &g_h1h[(size_t)scol[j] * 256];
            float wa0 = wbuf[j][h0], wb0 = wbuf[j][h1];
            float2 a0 = __half22float2(p0[t]);
            float2 b0 = __half22float2(p0[128 + t]);
            accA.x = fmaf(wa0, a0.x, accA.x); accA.y = fmaf(wa0, a0.y, accA.y);
            accB.x = fmaf(wb0, b0.x, accB.x); accB.y = fmaf(wb0, b0.y, accB.y);
        }
        __syncthreads();
    }

    // block-reduce denominators
#pragma unroll
    for (int h = 0; h < 4; h++)
#pragma unroll
        for (int off = 16; off; off >>= 1)
            ss[h] += __shfl_xor_sync(0xffffffffu, ss[h], off);
    if (lane == 0) { sred[0][w] = ss[0]; sred[1][w] = ss[1]; sred[2][w] = ss[2]; sred[3][w] = ss[3]; }
    __syncthreads();

    float inv[4];
#pragma unroll
    for (int h = 0; h < 4; h++) {
        float s = sred[h][0] + sred[h][1] + sred[h][2] + sred[h][3];
        inv[h] = (s > 0.f) ? 1.f / s : 0.f;   // deg-0 node -> out = bias
    }

    float* orow = &g_act1[(size_t)n * HC1];
    {
        float2 bv = *(const float2*)&b1[2 * t];
        float ox = accA.x * inv[h0] + bv.x;
        float oy = accA.y * inv[h0] + bv.y;
        ox = ox > 0.f ? ox : expm1f(ox);
        oy = oy > 0.f ? oy : expm1f(oy);
        *(float2*)&orow[2 * t] = make_float2(ox, oy);
    }
    {
        float2 bv = *(const float2*)&b1[256 + 2 * t];
        float ox = accB.x * inv[h1] + bv.x;
        float oy = accB.y * inv[h1] + bv.y;
        ox = ox > 0.f ? ox : expm1f(ox);
        oy = oy > 0.f ? oy : expm1f(oy);
        *(float2*)&orow[256 + 2 * t] = make_float2(ox, oy);
    }
}

// ---------------- layer 2 aggregation (fp16 gather) -> final output ----------------
__global__ void k_agg2(const float* __restrict__ b2, float* __restrict__ out) {
    int n = blockIdx.x;
    int t = threadIdx.x, lane = t & 31, w = t >> 5;
    int sub = t >> 6, tw = t & 63;
    int start = g_rowptr[n], end = g_rowptr[n + 1];
    float ed = g_edst2[n];

    __shared__ float wbuf[128];
    __shared__ int scol[128];
    __shared__ float sred[4];
    __shared__ float2 sacc[128];

    float2 acc = make_float2(0.f, 0.f);
    float ss = 0.f;

    for (int base = start; base < end; base += 128) {
        int i = base + t;
        if (i < end) {
            int sc = g_col[i];
            float wv = __expf(lrelu(g_esrc2[sc] + ed));
            ss += wv;
            wbuf[t] = wv;
            scol[t] = sc;
        }
        __syncthreads();
        int cnt = min(128, end - base);
        for (int j = sub; j < cnt; j += 2) {
            const __half2* p = &g_h3h[(size_t)scol[j] * 64];
            float wv = wbuf[j];
            float2 v = __half22float2(p[tw]);
            acc.x = fmaf(wv, v.x, acc.x);
            acc.y = fmaf(wv, v.y, acc.y);
        }
        __syncthreads();
    }

#pragma unroll
    for (int off = 16; off; off >>= 1) ss += __shfl_xor_sync(0xffffffffu, ss, off);
    if (lane == 0) sred[w] = ss;
    sacc[t] = acc;
    __syncthreads();

    if (t < 64) {
        float s = sred[0] + sred[1] + sred[2] + sred[3];
        float inv = (s > 0.f) ? 1.f / s : 0.f;
        float2 a0 = sacc[t], a1 = sacc[64 + t];
        float2 bv = *(const float2*)&b2[2 * t];
        float ox = (a0.x + a1.x) * inv + bv.x;
        float oy = (a0.y + a1.y) * inv + bv.y;
        *(float2*)&out[(size_t)n * C2 + 2 * t] = make_float2(ox, oy);
    }
}

// ---------------- launch ----------------
extern "C" void kernel_launch(void* const* d_in, const int* in_sizes, int n_in,
                              void* d_out, int out_size) {
    const float* x    = (const float*)d_in[0];
    const int*   ei   = (const int*)d_in[1];
    const float* sent = (const float*)d_in[2];
    const float* W1   = (const float*)d_in[3];
    const float* a1s  = (const float*)d_in[4];
    const float* a1d  = (const float*)d_in[5];
    const float* b1   = (const float*)d_in[6];
    const float* W2   = (const float*)d_in[7];
    const float* a2s  = (const float*)d_in[8];
    const float* a2d  = (const float*)d_in[9];
    const float* b2   = (const float*)d_in[10];
    float* out = (float*)d_out;

    int N = in_sizes[0] / SED;   // 20000
    int E = in_sizes[1] / 2;     // 320000
    int nb = (N + 511) / 512;    // scan blocks (<=64)

    float *p_act1, *p_c1;
    __half2 *p_h1h, *p_h3h;
    int *p_cnt;
    cudaGetSymbolAddress((void**)&p_h1h,  g_h1h);
    cudaGetSymbolAddress((void**)&p_h3h,  g_h3h);
    cudaGetSymbolAddress((void**)&p_act1, g_act1);
    cudaGetSymbolAddress((void**)&p_c1,   g_c1);
    cudaGetSymbolAddress((void**)&p_cnt,  g_cnt);

    // Side stream + events, created once on the first (non-captured) call.
    // Work per call is identical; these are host-side handles only.
    static cudaStream_t s2 = nullptr;
    static cudaEvent_t evF = nullptr, evJ = nullptr;
    if (s2 == nullptr) {
        cudaStreamCreateWithFlags(&s2, cudaStreamNonBlocking);
        cudaEventCreateWithFlags(&evF, cudaEventDisableTiming);
        cudaEventCreateWithFlags(&evJ, cudaEventDisableTiming);
    }

    // ---- fork: CSR build on s2, concurrent with layer-1 GEMM chain on stream 0 ----
    cudaEventRecord(evF, 0);
    cudaStreamWaitEvent(s2, evF, 0);

    // CSR build (dst-sorted) on s2
    cudaMemsetAsync(p_cnt, 0, N * sizeof(int), s2);
    k_count<<<(E + 255) / 256, 256, 0, s2>>>(ei, E);
    k_scan1<<<nb, 512, 0, s2>>>(N);
    k_scan3<<<(N + 255) / 256, 256, 0, s2>>>(N);
    k_scatter<<<(E + 255) / 256, 256, 0, s2>>>(ei, E);
    cudaEventRecord(evJ, s2);

    // Layer 1 GEMM chain on stream 0 (independent of CSR)
    cudaMemsetAsync(p_c1, 0, HC1 * sizeof(float));
    k_constvec<<<dim3(4, 6), 128>>>(sent, W1);
    k_gemm_tf32<<<dim3((N + 127) / 128, HC1 / 128), 256>>>(x, W1, p_h1h, p_c1, N, HC1, SED);
    k_edot1<<<N, 128>>>(a1s, a1d);

    // ---- join: agg1 needs CSR + edot1 ----
    cudaStreamWaitEvent(0, evJ, 0);
    k_agg1<<<N, 128>>>(b1);

    // Layer 2
    k_gemm_tf32<<<dim3((N + 127) / 128, C2 / 128), 256>>>(p_act1, W2, p_h3h, nullptr, N, C2, HC1);
    k_edot2<<<(N + 3) / 4, 128>>>(a2s, a2d, N);
    k_agg2<<<N, 128>>>(b2, out);
}